// round 15
// baseline (speedup 1.0000x reference)
#include <cuda_runtime.h>
#include <cstdint>

// ---------------------------------------------------------------------------
// CRF Viterbi decode, K=16 tags, T up to 1,000,000 steps.
//
//   2x k_dummy : align ncu -s 5 -c 1 capture onto k_chain.
//   K0 k_tr    : transpose feats [T][16] -> g_ftr[16][T] (bandwidth-parallel).
//   K1 k_chain : sequential bit-exact forward recurrence, 16 lanes = 1 warp.
//                Warp-synchronous smem broadcast (no BAR; in-order LSU makes
//                st.shared -> ld.shared RAW-safe within one converged warp).
//                ALL-SCALAR arithmetic: R14 profiling showed the f32x2 packed
//                path was issue-bound at ~92% with ~50 compiler MOVs/step from
//                u64 register pairing; scalar FADD (fma pipe) + FMNMX (alu
//                pipe) alternate across pipes at ~1 instr/cyc with zero churn.
//   K2 k_bp    : grid-parallel backpointers (first-max argmax, bit-exact).
//   K3 k_chunk : per-chunk 16-hypothesis backward chase.
//   K3b k_seed : sequential composition of chunk maps.
//   K4 k_out   : parallel select, FLOAT32 output.
// ---------------------------------------------------------------------------

#define T_MAX   1000000
#define KT      16
#define CHUNK   2048
#define NCHUNK_MAX ((T_MAX + CHUNK - 1) / CHUNK)   // 489

__device__ __align__(16) float         g_ftr[(size_t)KT * T_MAX];  // feats^T [j][t]
__device__ __align__(16) float         g_fvt[(size_t)KT * T_MAX];  // fv^T    [j][t]
__device__ __align__(16) unsigned char g_bp[(size_t)T_MAX * KT];
__device__ __align__(16) unsigned char g_p16[(size_t)T_MAX * KT];
__device__ __align__(16) unsigned char g_comp[NCHUNK_MAX * KT];
__device__ __align__(16) unsigned char g_seed[NCHUNK_MAX];

__global__ void k_dummy() {}

// ---------------------------------------------------------------------------
// K0: transpose feats [T][16] -> g_ftr[16][T_MAX]. 64-t x 16-j tiles.
// ---------------------------------------------------------------------------
__global__ void k_tr(const float* __restrict__ feats, int T)
{
    __shared__ float tile[16][65];
    int t0  = blockIdx.x * 64;
    int lin = threadIdx.x;            // 256 threads
    int jj  = lin & 15;
    int tb  = lin >> 4;               // 0..15
#pragma unroll
    for (int r = 0; r < 4; r++) {
        int tl = tb + r * 16;
        int t  = t0 + tl;
        tile[jj][tl] = (t < T) ? feats[(size_t)t * KT + jj] : 0.0f;
    }
    __syncthreads();
#pragma unroll
    for (int r = 0; r < 4; r++) {
        int idx = lin + r * 256;
        int j2  = idx >> 6;           // 0..15
        int tl  = idx & 63;
        int t   = t0 + tl;
        if (t < T) g_ftr[(size_t)j2 * T_MAX + t] = tile[j2][tl];
    }
}

// ---------------------------------------------------------------------------
// One warp-synchronous chain step (all scalar):
//   st.shared fv[j]; 4x ld.shared.v4.f32 (in-order LSU => RAW safe, no BAR);
//   fv' = max_p( fv[p] + a[p] ) + feat     (bit-exact vs reference)
// ---------------------------------------------------------------------------
__device__ __forceinline__ float chain_step(
    unsigned sbase, unsigned saddr_j, float fv, float feat, const float* a)
{
    asm volatile("st.shared.f32 [%0], %1;" :: "r"(saddr_j), "f"(fv) : "memory");
    float v0, v1, v2, v3, v4, v5, v6, v7;
    float v8, v9, v10, v11, v12, v13, v14, v15;
    asm volatile("ld.shared.v4.f32 {%0,%1,%2,%3}, [%4];"
                 : "=f"(v0), "=f"(v1), "=f"(v2), "=f"(v3)
                 : "r"(sbase) : "memory");
    asm volatile("ld.shared.v4.f32 {%0,%1,%2,%3}, [%4];"
                 : "=f"(v4), "=f"(v5), "=f"(v6), "=f"(v7)
                 : "r"(sbase + 16) : "memory");
    asm volatile("ld.shared.v4.f32 {%0,%1,%2,%3}, [%4];"
                 : "=f"(v8), "=f"(v9), "=f"(v10), "=f"(v11)
                 : "r"(sbase + 32) : "memory");
    asm volatile("ld.shared.v4.f32 {%0,%1,%2,%3}, [%4];"
                 : "=f"(v12), "=f"(v13), "=f"(v14), "=f"(v15)
                 : "r"(sbase + 48) : "memory");
    // one FADD per score (bit-exact vs reference)
    v0  += a[0];   v1  += a[1];   v2  += a[2];   v3  += a[3];
    v4  += a[4];   v5  += a[5];   v6  += a[6];   v7  += a[7];
    v8  += a[8];   v9  += a[9];   v10 += a[10];  v11 += a[11];
    v12 += a[12];  v13 += a[13];  v14 += a[14];  v15 += a[15];
    // exact max tree (fp max is order-independent)
    v0 = fmaxf(v0, v8);   v1 = fmaxf(v1, v9);
    v2 = fmaxf(v2, v10);  v3 = fmaxf(v3, v11);
    v4 = fmaxf(v4, v12);  v5 = fmaxf(v5, v13);
    v6 = fmaxf(v6, v14);  v7 = fmaxf(v7, v15);
    v0 = fmaxf(v0, v4);   v1 = fmaxf(v1, v5);
    v2 = fmaxf(v2, v6);   v3 = fmaxf(v3, v7);
    v0 = fmaxf(v0, v2);   v1 = fmaxf(v1, v3);
    v0 = fmaxf(v0, v1);
    return v0 + feat;
}

__global__ void __launch_bounds__(16, 1)
k_chain(const float* __restrict__ trans, int T)
{
    __shared__ __align__(64) float sS[16];
    const int j = threadIdx.x;        // tag

    unsigned sbase   = (unsigned)__cvta_generic_to_shared(&sS[0]);
    unsigned saddr_j = sbase + (unsigned)(j * 4);

    // A row j (transitions[next=j][prev=p]) -> registers
    float a[16];
#pragma unroll
    for (int q = 0; q < 4; q++) {
        float4 v = reinterpret_cast<const float4*>(trans)[j * 4 + q];
        a[4 * q + 0] = v.x; a[4 * q + 1] = v.y;
        a[4 * q + 2] = v.z; a[4 * q + 3] = v.w;
    }

    const float* fj = g_ftr + (size_t)j * T_MAX;   // my feat row (transposed)
    float*       oj = g_fvt + (size_t)j * T_MAX;   // my fv row (transposed)

    float fv = 0.0f;

    // Main loop: groups of 16 steps; group g prefetches group g+1.
    int G = (T >= 32) ? ((T - 16) / 16) : 0;

    float4 cur[4], nxt[4];
    if (G > 0) {
#pragma unroll
        for (int q = 0; q < 4; q++) cur[q] = *(const float4*)(fj + q * 4);
    }

    for (int g = 0; g < G; g++) {
        const float* pf = fj + (size_t)(g + 1) * 16;
#pragma unroll
        for (int q = 0; q < 4; q++) nxt[q] = *(const float4*)(pf + q * 4);
        float* po = oj + (size_t)g * 16;
#pragma unroll
        for (int q = 0; q < 4; q++) {
            float4 f4 = cur[q];
            float4 acc;
            acc.x = fv = chain_step(sbase, saddr_j, fv, f4.x, a);
            acc.y = fv = chain_step(sbase, saddr_j, fv, f4.y, a);
            acc.z = fv = chain_step(sbase, saddr_j, fv, f4.z, a);
            acc.w = fv = chain_step(sbase, saddr_j, fv, f4.w, a);
            *(float4*)(po + q * 4) = acc;
        }
#pragma unroll
        for (int q = 0; q < 4; q++) cur[q] = nxt[q];
    }

    // Epilogue: remaining steps, scalar.
    for (int t = G * 16; t < T; t++) {
        fv = chain_step(sbase, saddr_j, fv, fj[t], a);
        oj[t] = fv;
    }
}

// ---------------------------------------------------------------------------
// K2: backpointers, grid-parallel. Thread handles (t, i).
// Strict '>' ascending scan keeps FIRST max (jnp.argmax). Scores recomputed
// with the identical single FADD -> bit-exact. Reads transposed fv.
// ---------------------------------------------------------------------------
__global__ void k_bp(const float* __restrict__ trans, int T)
{
    int idx = blockIdx.x * blockDim.x + threadIdx.x;
    if (idx >= T * KT) return;
    int t = idx >> 4;
    int i = idx & 15;

    float pv[16];
    if (t == 0) {
#pragma unroll
        for (int p = 0; p < 16; p++) pv[p] = 0.0f;
    } else {
#pragma unroll
        for (int p = 0; p < 16; p++)
            pv[p] = g_fvt[(size_t)p * T_MAX + (t - 1)];
    }

    float a[16];
#pragma unroll
    for (int q = 0; q < 4; q++) {
        float4 v = reinterpret_cast<const float4*>(trans)[i * 4 + q];
        a[4 * q + 0] = v.x; a[4 * q + 1] = v.y;
        a[4 * q + 2] = v.z; a[4 * q + 3] = v.w;
    }

    float best = pv[0] + a[0];
    int bi = 0;
#pragma unroll
    for (int p = 1; p < 16; p++) {
        float sc = pv[p] + a[p];
        if (sc > best) { best = sc; bi = p; }
    }
    g_bp[idx] = (unsigned char)bi;
}

// ---------------------------------------------------------------------------
// K3: per-chunk backward chase of all 16 exit-tag hypotheses.
// ---------------------------------------------------------------------------
__global__ void k_chunk(int T)
{
    __shared__ __align__(16) unsigned char sbp[CHUNK * KT];   // 32 KB
    int c = blockIdx.x;
    int s = c * CHUNK;
    int L = min(CHUNK, T - s);

    const int4* src = reinterpret_cast<const int4*>(g_bp + (size_t)s * KT);
    int4* dst = reinterpret_cast<int4*>(sbp);
    for (int i = threadIdx.x; i < L; i += blockDim.x) dst[i] = src[i];
    __syncthreads();

    if (threadIdx.x < 16) {
        int cur = threadIdx.x;
        for (int tt = L - 1; tt >= 0; tt--) {
            cur = sbp[tt * KT + cur];
            g_p16[(size_t)(s + tt) * KT + threadIdx.x] = (unsigned char)cur;
        }
        g_comp[c * KT + threadIdx.x] = (unsigned char)cur;
    }
}

// ---------------------------------------------------------------------------
// K3b: compose chunk maps right-to-left. Z starts at argmax(final fv).
// ---------------------------------------------------------------------------
__global__ void k_seed(int T, int C)
{
    __shared__ __align__(16) unsigned char sc[NCHUNK_MAX * KT];
    for (int i = threadIdx.x; i < C * KT; i += blockDim.x) sc[i] = g_comp[i];
    __syncthreads();

    if (threadIdx.x == 0) {
        float best = g_fvt[(size_t)0 * T_MAX + (T - 1)];
        int Z = 0;
#pragma unroll
        for (int i = 1; i < 16; i++) {
            float v = g_fvt[(size_t)i * T_MAX + (T - 1)];
            if (v > best) { best = v; Z = i; }
        }
        for (int c = C - 1; c >= 0; c--) {
            g_seed[c] = (unsigned char)Z;
            Z = sc[c * KT + Z];
        }
    }
}

// ---------------------------------------------------------------------------
// K4: final select.  out[t] = (float) path16[t][ seed[chunk(t)] ]
// ---------------------------------------------------------------------------
__global__ void k_out(float* __restrict__ out, int T)
{
    int t = blockIdx.x * blockDim.x + threadIdx.x;
    if (t < T) {
        int h = g_seed[t / CHUNK];
        out[t] = (float)g_p16[(size_t)t * KT + h];
    }
}

// ---------------------------------------------------------------------------
extern "C" void kernel_launch(void* const* d_in, const int* in_sizes, int n_in,
                              void* d_out, int out_size)
{
    // Input autodetect: transitions = 256-element tensor; sentence = large.
    int fi = 0;
    if (n_in >= 2 && in_sizes[1] > in_sizes[0]) fi = 1;
    const float* feats = (const float*)d_in[fi];
    const float* trans = (const float*)d_in[1 - fi];

    int T = in_sizes[fi] / KT;
    if (T > T_MAX) T = T_MAX;
    if (out_size > 0 && out_size < T) T = out_size;
    if (T < 1) return;
    int C = (T + CHUNK - 1) / CHUNK;

    // ncu alignment: 2 harness launches + 2 dummies + k_tr = 5 skipped,
    // capture lands on k_chain.
    k_dummy<<<1, 32>>>();
    k_dummy<<<1, 32>>>();

    k_tr<<<(T + 63) / 64, 256>>>(feats, T);
    k_chain<<<1, 16>>>(trans, T);
    k_bp<<<(T * KT + 255) / 256, 256>>>(trans, T);
    k_chunk<<<C, 128>>>(T);
    k_seed<<<1, 128>>>(T, C);
    k_out<<<(T + 255) / 256, 256>>>((float*)d_out, T);
}

// round 17
// speedup vs baseline: 1.0498x; 1.0498x over previous
#include <cuda_runtime.h>
#include <cstdint>

// ---------------------------------------------------------------------------
// CRF Viterbi decode, K=16 tags, T up to 1,000,000 steps.
//
//   2x k_dummy : align ncu -s 5 -c 1 capture onto k_chain.
//   K0 k_tr    : transpose feats [T][16] -> g_ftr[16][T] (bandwidth-parallel).
//   K1 k_chain : sequential bit-exact forward recurrence, 16 lanes = 1 warp.
//                Warp-synchronous smem broadcast (no BAR). Packed add.rn.f32x2
//                (R14 core, best). NEW: the STS->LDS window (smem has no
//                store-forwarding; dependent LDS waits for STS commit) is
//                filled with useful work -- the previous step's fv store and
//                the feat prefetch -- pinned there by the surrounding memory-
//                clobber asms. fv OUTPUT is row-major [t][16] so the per-step
//                store is one coalesced 64B wavefront (transposed stores were
//                16 scattered wavefronts fighting the LDS in the in-order LSU).
//   K2 k_bp    : grid-parallel backpointers (first-max argmax, bit-exact).
//   K3 k_chunk : per-chunk 16-hypothesis backward chase.
//   K3b k_seed : sequential composition of chunk maps.
//   K4 k_out   : parallel select, FLOAT32 output.
// ---------------------------------------------------------------------------

#define T_MAX   1000000
#define KT      16
#define CHUNK   2048
#define NCHUNK_MAX ((T_MAX + CHUNK - 1) / CHUNK)   // 489

__device__ __align__(16) float         g_ftr[(size_t)KT * T_MAX];      // feats^T [j][t]
// fv row-major [t][16] with a 16-float front guard: step t stores fv_{t-1}
// at index (t-1)*16+j; for t=0 that lands in the guard (branch-free).
__device__ __align__(64) float         g_fv_buf[16 + (size_t)T_MAX * KT];
#define G_FV (g_fv_buf + 16)
__device__ __align__(16) unsigned char g_bp[(size_t)T_MAX * KT];
__device__ __align__(16) unsigned char g_p16[(size_t)T_MAX * KT];
__device__ __align__(16) unsigned char g_comp[NCHUNK_MAX * KT];
__device__ __align__(16) unsigned char g_seed[NCHUNK_MAX];

// Packed fp32 helpers. add.rn.f32x2 = two independent IEEE-rn fp32 adds ->
// bit-exact vs scalar FADD.
#define ADDX2(out, x, y) \
    asm("add.rn.f32x2 %0, %1, %2;" : "=l"(out) : "l"(x), "l"(y))
#define PKX2(out, lo, hi) \
    asm("mov.b64 %0, {%1, %2};" : "=l"(out) : "f"(lo), "f"(hi))
#define UNPKX2(lo, hi, in) \
    asm("mov.b64 {%0, %1}, %2;" : "=f"(lo), "=f"(hi) : "l"(in))

__global__ void k_dummy() {}

// ---------------------------------------------------------------------------
// K0: transpose feats [T][16] -> g_ftr[16][T_MAX]. 64-t x 16-j tiles.
// ---------------------------------------------------------------------------
__global__ void k_tr(const float* __restrict__ feats, int T)
{
    __shared__ float tile[16][65];
    int t0  = blockIdx.x * 64;
    int lin = threadIdx.x;            // 256 threads
    int jj  = lin & 15;
    int tb  = lin >> 4;               // 0..15
#pragma unroll
    for (int r = 0; r < 4; r++) {
        int tl = tb + r * 16;
        int t  = t0 + tl;
        tile[jj][tl] = (t < T) ? feats[(size_t)t * KT + jj] : 0.0f;
    }
    __syncthreads();
#pragma unroll
    for (int r = 0; r < 4; r++) {
        int idx = lin + r * 256;
        int j2  = idx >> 6;           // 0..15
        int tl  = idx & 63;
        int t   = t0 + tl;
        if (t < T) g_ftr[(size_t)j2 * T_MAX + t] = tile[j2][tl];
    }
}

// ---------------------------------------------------------------------------
// Core of one chain step AFTER the STS+gap: loads broadcast, packed adds,
// exact max tree, +feat.  (bit-exact: one FADD per score, order-independent
// fp max, one feat FADD — identical to the reference computation)
// ---------------------------------------------------------------------------
#define STEP_TAIL(FEAT)                                                       \
    do {                                                                      \
        unsigned long long w0, w1, w2, w3, w4, w5, w6, w7;                    \
        asm volatile("ld.shared.v2.b64 {%0,%1}, [%2];"                        \
                     : "=l"(w0), "=l"(w1) : "r"(sbase)      : "memory");      \
        asm volatile("ld.shared.v2.b64 {%0,%1}, [%2];"                        \
                     : "=l"(w2), "=l"(w3) : "r"(sbase + 16) : "memory");      \
        asm volatile("ld.shared.v2.b64 {%0,%1}, [%2];"                        \
                     : "=l"(w4), "=l"(w5) : "r"(sbase + 32) : "memory");      \
        asm volatile("ld.shared.v2.b64 {%0,%1}, [%2];"                        \
                     : "=l"(w6), "=l"(w7) : "r"(sbase + 48) : "memory");      \
        unsigned long long c0, c1, c2, c3, c4, c5, c6, c7;                    \
        ADDX2(c0, w0, k0);  ADDX2(c1, w1, k1);                                \
        ADDX2(c2, w2, k2);  ADDX2(c3, w3, k3);                                \
        ADDX2(c4, w4, k4);  ADDX2(c5, w5, k5);                                \
        ADDX2(c6, w6, k6);  ADDX2(c7, w7, k7);                                \
        float v0, v1, v2, v3, v4, v5, v6, v7;                                 \
        float v8, v9, v10, v11, v12, v13, v14, v15;                           \
        UNPKX2(v0,  v1,  c0);  UNPKX2(v2,  v3,  c1);                          \
        UNPKX2(v4,  v5,  c2);  UNPKX2(v6,  v7,  c3);                          \
        UNPKX2(v8,  v9,  c4);  UNPKX2(v10, v11, c5);                          \
        UNPKX2(v12, v13, c6);  UNPKX2(v14, v15, c7);                          \
        v0 = fmaxf(v0, v8);   v1 = fmaxf(v1, v9);                             \
        v2 = fmaxf(v2, v10);  v3 = fmaxf(v3, v11);                            \
        v4 = fmaxf(v4, v12);  v5 = fmaxf(v5, v13);                            \
        v6 = fmaxf(v6, v14);  v7 = fmaxf(v7, v15);                            \
        v0 = fmaxf(v0, v4);   v1 = fmaxf(v1, v5);                             \
        v2 = fmaxf(v2, v6);   v3 = fmaxf(v3, v7);                             \
        v0 = fmaxf(v0, v2);   v1 = fmaxf(v1, v3);                             \
        v0 = fmaxf(v0, v1);                                                   \
        fv = v0 + (FEAT);                                                     \
    } while (0)

#define STS_FV() \
    asm volatile("st.shared.f32 [%0], %1;" :: "r"(saddr_j), "f"(fv) : "memory")

__global__ void __launch_bounds__(16, 1)
k_chain(const float* __restrict__ trans, int T)
{
    __shared__ __align__(64) float sS[16];
    const int j = threadIdx.x;        // tag

    unsigned sbase   = (unsigned)__cvta_generic_to_shared(&sS[0]);
    unsigned saddr_j = sbase + (unsigned)(j * 4);

    // A row j packed into 8 f32x2 constants
    unsigned long long k0, k1, k2, k3, k4, k5, k6, k7;
    {
        float4 q0 = reinterpret_cast<const float4*>(trans)[j * 4 + 0];
        float4 q1 = reinterpret_cast<const float4*>(trans)[j * 4 + 1];
        float4 q2 = reinterpret_cast<const float4*>(trans)[j * 4 + 2];
        float4 q3 = reinterpret_cast<const float4*>(trans)[j * 4 + 3];
        PKX2(k0, q0.x, q0.y);  PKX2(k1, q0.z, q0.w);
        PKX2(k2, q1.x, q1.y);  PKX2(k3, q1.z, q1.w);
        PKX2(k4, q2.x, q2.y);  PKX2(k5, q2.z, q2.w);
        PKX2(k6, q3.x, q3.y);  PKX2(k7, q3.z, q3.w);
    }

    const float* fj = g_ftr + (size_t)j * T_MAX;   // my feat row (transposed)

    float fv = 0.0f;

    // Main loop: groups of 16 steps; group g prefetches group g+1's feats.
    int G = (T >= 32) ? ((T - 16) / 16) : 0;

    float4 cur[4], nxt[4];
    if (G > 0) {
#pragma unroll
        for (int q = 0; q < 4; q++) cur[q] = *(const float4*)(fj + q * 4);
    }

    // Store pointer: step t (global) stores fv_{t-1} at G_FV[(t-1)*16 + j].
    // For t=0 this hits the front guard (g_fv_buf[j]) — branch-free.
    float* so = G_FV + j;                          // row-major, coalesced

    for (int g = 0; g < G; g++) {
        const float* pf = fj + (size_t)(g + 1) * 16;
#pragma unroll
        for (int q = 0; q < 4; q++) {
            float4 f4 = cur[q];
            // ---- step u = 4q+0: gap = prev-fv store + quad feat prefetch ----
            STS_FV();
            so[(q * 4 + 0 - 1) * KT] = fv;         // coalesced STG.32
            nxt[q] = *(const float4*)(pf + q * 4); // LDG.128 prefetch
            STEP_TAIL(f4.x);
            // ---- step u = 4q+1 ----
            STS_FV();
            so[(q * 4 + 1 - 1) * KT] = fv;
            STEP_TAIL(f4.y);
            // ---- step u = 4q+2 ----
            STS_FV();
            so[(q * 4 + 2 - 1) * KT] = fv;
            STEP_TAIL(f4.z);
            // ---- step u = 4q+3 ----
            STS_FV();
            so[(q * 4 + 3 - 1) * KT] = fv;
            STEP_TAIL(f4.w);
        }
#pragma unroll
        for (int q = 0; q < 4; q++) cur[q] = nxt[q];
        so += 16 * KT;
    }

    // Store the last main-loop fv (index 16G-1), then run the epilogue.
    if (G > 0) G_FV[((size_t)16 * G - 1) * KT + j] = fv;
    for (int t = G * 16; t < T; t++) {
        float ft = fj[t];
        STS_FV();
        STEP_TAIL(ft);
        G_FV[(size_t)t * KT + j] = fv;
    }
}

// ---------------------------------------------------------------------------
// K2: backpointers, grid-parallel. Thread handles (t, i).
// Strict '>' ascending scan keeps FIRST max (jnp.argmax). Scores recomputed
// with the identical single FADD -> bit-exact. Reads row-major fv.
// ---------------------------------------------------------------------------
__global__ void k_bp(const float* __restrict__ trans, int T)
{
    int idx = blockIdx.x * blockDim.x + threadIdx.x;
    if (idx >= T * KT) return;
    int t = idx >> 4;
    int i = idx & 15;

    float pv[16];
    if (t == 0) {
#pragma unroll
        for (int p = 0; p < 16; p++) pv[p] = 0.0f;
    } else {
        const float4* row = reinterpret_cast<const float4*>(G_FV + (size_t)(t - 1) * KT);
#pragma unroll
        for (int q = 0; q < 4; q++) {
            float4 v = row[q];
            pv[4 * q + 0] = v.x; pv[4 * q + 1] = v.y;
            pv[4 * q + 2] = v.z; pv[4 * q + 3] = v.w;
        }
    }

    float a[16];
#pragma unroll
    for (int q = 0; q < 4; q++) {
        float4 v = reinterpret_cast<const float4*>(trans)[i * 4 + q];
        a[4 * q + 0] = v.x; a[4 * q + 1] = v.y;
        a[4 * q + 2] = v.z; a[4 * q + 3] = v.w;
    }

    float best = pv[0] + a[0];
    int bi = 0;
#pragma unroll
    for (int p = 1; p < 16; p++) {
        float sc = pv[p] + a[p];
        if (sc > best) { best = sc; bi = p; }
    }
    g_bp[idx] = (unsigned char)bi;
}

// ---------------------------------------------------------------------------
// K3: per-chunk backward chase of all 16 exit-tag hypotheses.
// ---------------------------------------------------------------------------
__global__ void k_chunk(int T)
{
    __shared__ __align__(16) unsigned char sbp[CHUNK * KT];   // 32 KB
    int c = blockIdx.x;
    int s = c * CHUNK;
    int L = min(CHUNK, T - s);

    const int4* src = reinterpret_cast<const int4*>(g_bp + (size_t)s * KT);
    int4* dst = reinterpret_cast<int4*>(sbp);
    for (int i = threadIdx.x; i < L; i += blockDim.x) dst[i] = src[i];
    __syncthreads();

    if (threadIdx.x < 16) {
        int cur = threadIdx.x;
        for (int tt = L - 1; tt >= 0; tt--) {
            cur = sbp[tt * KT + cur];
            g_p16[(size_t)(s + tt) * KT + threadIdx.x] = (unsigned char)cur;
        }
        g_comp[c * KT + threadIdx.x] = (unsigned char)cur;
    }
}

// ---------------------------------------------------------------------------
// K3b: compose chunk maps right-to-left. Z starts at argmax(final fv).
// ---------------------------------------------------------------------------
__global__ void k_seed(int T, int C)
{
    __shared__ __align__(16) unsigned char sc[NCHUNK_MAX * KT];
    for (int i = threadIdx.x; i < C * KT; i += blockDim.x) sc[i] = g_comp[i];
    __syncthreads();

    if (threadIdx.x == 0) {
        const float* f = G_FV + (size_t)(T - 1) * KT;
        float best = f[0];
        int Z = 0;
#pragma unroll
        for (int i = 1; i < 16; i++) {
            float v = f[i];
            if (v > best) { best = v; Z = i; }
        }
        for (int c = C - 1; c >= 0; c--) {
            g_seed[c] = (unsigned char)Z;
            Z = sc[c * KT + Z];
        }
    }
}

// ---------------------------------------------------------------------------
// K4: final select.  out[t] = (float) path16[t][ seed[chunk(t)] ]
// ---------------------------------------------------------------------------
__global__ void k_out(float* __restrict__ out, int T)
{
    int t = blockIdx.x * blockDim.x + threadIdx.x;
    if (t < T) {
        int h = g_seed[t / CHUNK];
        out[t] = (float)g_p16[(size_t)t * KT + h];
    }
}

// ---------------------------------------------------------------------------
extern "C" void kernel_launch(void* const* d_in, const int* in_sizes, int n_in,
                              void* d_out, int out_size)
{
    // Input autodetect: transitions = 256-element tensor; sentence = large.
    int fi = 0;
    if (n_in >= 2 && in_sizes[1] > in_sizes[0]) fi = 1;
    const float* feats = (const float*)d_in[fi];
    const float* trans = (const float*)d_in[1 - fi];

    int T = in_sizes[fi] / KT;
    if (T > T_MAX) T = T_MAX;
    if (out_size > 0 && out_size < T) T = out_size;
    if (T < 1) return;
    int C = (T + CHUNK - 1) / CHUNK;

    // ncu alignment: 2 harness launches + 2 dummies + k_tr = 5 skipped,
    // capture lands on k_chain.
    k_dummy<<<1, 32>>>();
    k_dummy<<<1, 32>>>();

    k_tr<<<(T + 63) / 64, 256>>>(feats, T);
    k_chain<<<1, 16>>>(trans, T);
    k_bp<<<(T * KT + 255) / 256, 256>>>(trans, T);
    k_chunk<<<C, 128>>>(T);
    k_seed<<<1, 128>>>(T, C);
    k_out<<<(T + 255) / 256, 256>>>((float*)d_out, T);
}